// round 5
// baseline (speedup 1.0000x reference)
#include <cuda_runtime.h>
#include <cuda_fp16.h>
#include <cstdint>

#define N_NODES 100000
#define D 256
#define MAX_E 3200000

#define SCAN_CHUNK 4096
#define SCAN_BLOCKS ((N_NODES + SCAN_CHUNK - 1) / SCAN_CHUNK)   // 25

// Static device scratch (allocation-free rule)
__device__ __half g_support[(size_t)N_NODES * D];   // X @ W in fp16 (51.2 MB)
__device__ int    g_count [N_NODES];
__device__ int    g_offset[N_NODES];
__device__ int    g_cursor[N_NODES];
__device__ int    g_bsum  [SCAN_BLOCKS];
__device__ uint2  g_csr   [MAX_E];                  // {col, val bits}

// ---------------------------------------------------------------------------
// Kernel 1: SGEMM  support = X[100000,256] @ W[256,256], fp32 math, fp16 store
// 128x128 tile, BK=16, 256 threads, 8x8 per thread (2x2 groups of 4x4).
// ---------------------------------------------------------------------------
__global__ __launch_bounds__(256) void gemm_kernel(const float* __restrict__ A,
                                                   const float* __restrict__ B) {
    const int BM = 128, BK = 16;
    __shared__ float As[BK][BM + 4];
    __shared__ float Bs[BK][128];

    int tid = threadIdx.x;
    int tx  = tid & 15;
    int ty  = tid >> 4;
    int blockRow = blockIdx.y * BM;
    int blockCol = blockIdx.x * 128;

    float acc[2][2][4][4] = {};

    for (int k0 = 0; k0 < D; k0 += BK) {
        // A tile 128x16 = 512 float4, 2 per thread (transposed store)
        #pragma unroll
        for (int i = 0; i < 2; i++) {
            int f = tid + i * 256;
            int r = f >> 2;
            int c = (f & 3) * 4;
            int row = blockRow + r;
            float4 v = make_float4(0.f, 0.f, 0.f, 0.f);
            if (row < N_NODES)
                v = *reinterpret_cast<const float4*>(&A[(size_t)row * D + k0 + c]);
            As[c + 0][r] = v.x;
            As[c + 1][r] = v.y;
            As[c + 2][r] = v.z;
            As[c + 3][r] = v.w;
        }
        // B tile 16x128 = 512 float4, 2 per thread
        #pragma unroll
        for (int i = 0; i < 2; i++) {
            int f = tid + i * 256;
            int r = f >> 5;
            int c = (f & 31) * 4;
            *reinterpret_cast<float4*>(&Bs[r][c]) =
                *reinterpret_cast<const float4*>(&B[(size_t)(k0 + r) * D + blockCol + c]);
        }
        __syncthreads();

        #pragma unroll
        for (int k = 0; k < BK; k++) {
            float4 a0 = *reinterpret_cast<const float4*>(&As[k][ty * 4]);
            float4 a1 = *reinterpret_cast<const float4*>(&As[k][ty * 4 + 64]);
            float4 b0 = *reinterpret_cast<const float4*>(&Bs[k][tx * 4]);
            float4 b1 = *reinterpret_cast<const float4*>(&Bs[k][tx * 4 + 64]);
            float a[2][4] = {{a0.x, a0.y, a0.z, a0.w}, {a1.x, a1.y, a1.z, a1.w}};
            float b[2][4] = {{b0.x, b0.y, b0.z, b0.w}, {b1.x, b1.y, b1.z, b1.w}};
            #pragma unroll
            for (int ia = 0; ia < 2; ia++)
                #pragma unroll
                for (int ib = 0; ib < 2; ib++)
                    #pragma unroll
                    for (int i = 0; i < 4; i++)
                        #pragma unroll
                        for (int j = 0; j < 4; j++)
                            acc[ia][ib][i][j] += a[ia][i] * b[ib][j];
        }
        __syncthreads();
    }

    #pragma unroll
    for (int ia = 0; ia < 2; ia++) {
        #pragma unroll
        for (int i = 0; i < 4; i++) {
            int row = blockRow + ia * 64 + ty * 4 + i;
            if (row >= N_NODES) continue;
            #pragma unroll
            for (int ib = 0; ib < 2; ib++) {
                int col = blockCol + ib * 64 + tx * 4;
                __half2 h0 = __float22half2_rn(make_float2(acc[ia][ib][i][0], acc[ia][ib][i][1]));
                __half2 h1 = __float22half2_rn(make_float2(acc[ia][ib][i][2], acc[ia][ib][i][3]));
                uint2 pk = make_uint2(*reinterpret_cast<unsigned*>(&h0),
                                      *reinterpret_cast<unsigned*>(&h1));
                *reinterpret_cast<uint2*>(&g_support[(size_t)row * D + col]) = pk;
            }
        }
    }
}

// ---------------------------------------------------------------------------
// CSR construction
// ---------------------------------------------------------------------------
__global__ __launch_bounds__(256) void zero_count_kernel() {
    int i = blockIdx.x * blockDim.x + threadIdx.x;
    if (i < N_NODES) g_count[i] = 0;
}

__global__ __launch_bounds__(256) void hist_kernel(const int* __restrict__ adj_row, int nE) {
    int e = blockIdx.x * blockDim.x + threadIdx.x;
    if (e < nE) atomicAdd(&g_count[adj_row[e]], 1);
}

// Scan stage 1: per-block local exclusive scan of 4096 counts (4/thread).
__global__ __launch_bounds__(1024) void scan1_kernel() {
    __shared__ int sh[1024];
    int b = blockIdx.x, t = threadIdx.x;
    int base = b * SCAN_CHUNK + t * 4;

    int c[4];
    #pragma unroll
    for (int i = 0; i < 4; i++)
        c[i] = (base + i < N_NODES) ? g_count[base + i] : 0;
    int s = c[0] + c[1] + c[2] + c[3];

    sh[t] = s;
    __syncthreads();
    #pragma unroll
    for (int off = 1; off < 1024; off <<= 1) {
        int v = (t >= off) ? sh[t - off] : 0;
        __syncthreads();
        sh[t] += v;
        __syncthreads();
    }

    int run = (t == 0) ? 0 : sh[t - 1];
    #pragma unroll
    for (int i = 0; i < 4; i++) {
        if (base + i < N_NODES) g_offset[base + i] = run;
        run += c[i];
    }
    if (t == 1023) g_bsum[b] = sh[1023];
}

// Scan stage 2: each block adds the prefix of preceding block sums.
__global__ __launch_bounds__(1024) void scan2_kernel() {
    __shared__ int s_pre;
    int b = blockIdx.x, t = threadIdx.x;

    if (t < 32) {
        int s = 0;
        for (int i = t; i < b; i += 32) s += g_bsum[i];
        #pragma unroll
        for (int o = 16; o > 0; o >>= 1)
            s += __shfl_down_sync(0xFFFFFFFF, s, o);
        if (t == 0) s_pre = s;
    }
    __syncthreads();
    int pre = s_pre;

    int base = b * SCAN_CHUNK + t * 4;
    #pragma unroll
    for (int i = 0; i < 4; i++) {
        int idx = base + i;
        if (idx < N_NODES) {
            int off = g_offset[idx] + pre;
            g_offset[idx] = off;
            g_cursor[idx] = off;
        }
    }
}

__global__ __launch_bounds__(256) void build_kernel(const int* __restrict__ adj_row,
                                                    const int* __restrict__ adj_col,
                                                    const float* __restrict__ adj_val,
                                                    int nE) {
    int e = blockIdx.x * blockDim.x + threadIdx.x;
    if (e >= nE) return;
    int r = adj_row[e];
    int pos = atomicAdd(&g_cursor[r], 1);
    g_csr[pos] = make_uint2((unsigned)adj_col[e], __float_as_uint(adj_val[e]));
}

// ---------------------------------------------------------------------------
// CSR SpMM: warp per row, lane owns 8 halves (one uint4 / 16B per edge),
// fp32 accumulate, 4x unrolled gather, bias fused.
// ---------------------------------------------------------------------------
__device__ __forceinline__ void fma_halves(float acc[8], uint4 x, float v) {
    __half2* h = reinterpret_cast<__half2*>(&x);
    #pragma unroll
    for (int i = 0; i < 4; i++) {
        float2 f = __half22float2(h[i]);
        acc[i * 2 + 0] += f.x * v;
        acc[i * 2 + 1] += f.y * v;
    }
}

__global__ __launch_bounds__(256) void spmm_kernel(const float* __restrict__ bias,
                                                   float* __restrict__ out) {
    int gtid = blockIdx.x * blockDim.x + threadIdx.x;
    int r    = gtid >> 5;
    int lane = gtid & 31;
    if (r >= N_NODES) return;

    int start = g_offset[r];
    int end   = start + g_count[r];

    float acc[8] = {};

    int p = start;
    for (; p + 3 < end; p += 4) {
        uint2 e0 = g_csr[p + 0];
        uint2 e1 = g_csr[p + 1];
        uint2 e2 = g_csr[p + 2];
        uint2 e3 = g_csr[p + 3];
        uint4 x0 = *(reinterpret_cast<const uint4*>(g_support + (size_t)e0.x * D) + lane);
        uint4 x1 = *(reinterpret_cast<const uint4*>(g_support + (size_t)e1.x * D) + lane);
        uint4 x2 = *(reinterpret_cast<const uint4*>(g_support + (size_t)e2.x * D) + lane);
        uint4 x3 = *(reinterpret_cast<const uint4*>(g_support + (size_t)e3.x * D) + lane);
        fma_halves(acc, x0, __uint_as_float(e0.y));
        fma_halves(acc, x1, __uint_as_float(e1.y));
        fma_halves(acc, x2, __uint_as_float(e2.y));
        fma_halves(acc, x3, __uint_as_float(e3.y));
    }
    for (; p < end; p++) {
        uint2 e = g_csr[p];
        uint4 x = *(reinterpret_cast<const uint4*>(g_support + (size_t)e.x * D) + lane);
        fma_halves(acc, x, __uint_as_float(e.y));
    }

    const float4* bp = reinterpret_cast<const float4*>(bias) + lane * 2;
    float4 b0 = bp[0], b1 = bp[1];
    acc[0] += b0.x; acc[1] += b0.y; acc[2] += b0.z; acc[3] += b0.w;
    acc[4] += b1.x; acc[5] += b1.y; acc[6] += b1.z; acc[7] += b1.w;

    float4* dst = reinterpret_cast<float4*>(out + (size_t)r * D) + lane * 2;
    dst[0] = make_float4(acc[0], acc[1], acc[2], acc[3]);
    dst[1] = make_float4(acc[4], acc[5], acc[6], acc[7]);
}

// ---------------------------------------------------------------------------
// Launch
// ---------------------------------------------------------------------------
extern "C" void kernel_launch(void* const* d_in, const int* in_sizes, int n_in,
                              void* d_out, int out_size) {
    const float* X    = (const float*)d_in[0];
    const int*   arow = (const int*)  d_in[1];
    const int*   acol = (const int*)  d_in[2];
    const float* aval = (const float*)d_in[3];
    const float* W    = (const float*)d_in[4];
    const float* bias = (const float*)d_in[5];
    float*       out  = (float*)d_out;

    int nE = in_sizes[1];
    if (nE > MAX_E) nE = MAX_E;

    // 1) support = X @ W  (fp16 store)
    dim3 gemm_grid(D / 128, (N_NODES + 127) / 128);
    gemm_kernel<<<gemm_grid, 256>>>(X, W);

    // 2) CSR build (parallel scan)
    zero_count_kernel<<<(N_NODES + 255) / 256, 256>>>();
    hist_kernel<<<(nE + 255) / 256, 256>>>(arow, nE);
    scan1_kernel<<<SCAN_BLOCKS, 1024>>>();
    scan2_kernel<<<SCAN_BLOCKS, 1024>>>();
    build_kernel<<<(nE + 255) / 256, 256>>>(arow, acol, aval, nE);

    // 3) SpMM (warp per row), bias fused
    long long total_threads = (long long)N_NODES * 32;
    int nblk = (int)((total_threads + 255) / 256);
    spmm_kernel<<<nblk, 256>>>(bias, out);
}

// round 7
// speedup vs baseline: 1.3794x; 1.3794x over previous
#include <cuda_runtime.h>
#include <cuda_fp16.h>
#include <cstdint>

#define N_NODES 100000
#define D 256
#define MAX_E 3200000

#define SCAN_CHUNK 4096
#define SCAN_BLOCKS ((N_NODES + SCAN_CHUNK - 1) / SCAN_CHUNK)   // 25

// Static device scratch (allocation-free rule)
__device__ __half g_support[(size_t)N_NODES * D];   // X @ W in fp16 (51.2 MB)
__device__ int    g_count [N_NODES];
__device__ int    g_offset[N_NODES];
__device__ int    g_cursor[N_NODES];
__device__ int    g_bsum  [SCAN_BLOCKS];
__device__ uint2  g_csr   [MAX_E];                  // {col, val bits}

// ---------------------------------------------------------------------------
// Kernel 1: SGEMM  support = X[100000,256] @ W[256,256], fp32 math, fp16 store
// 128x128 tile, BK=16, 256 threads, 8x8 per thread (2x2 groups of 4x4).
// ---------------------------------------------------------------------------
__global__ __launch_bounds__(256) void gemm_kernel(const float* __restrict__ A,
                                                   const float* __restrict__ B) {
    const int BM = 128, BK = 16;
    __shared__ float As[BK][BM + 4];
    __shared__ float Bs[BK][128];

    int tid = threadIdx.x;
    int tx  = tid & 15;
    int ty  = tid >> 4;
    int blockRow = blockIdx.y * BM;
    int blockCol = blockIdx.x * 128;

    float acc[2][2][4][4] = {};

    for (int k0 = 0; k0 < D; k0 += BK) {
        #pragma unroll
        for (int i = 0; i < 2; i++) {
            int f = tid + i * 256;
            int r = f >> 2;
            int c = (f & 3) * 4;
            int row = blockRow + r;
            float4 v = make_float4(0.f, 0.f, 0.f, 0.f);
            if (row < N_NODES)
                v = *reinterpret_cast<const float4*>(&A[(size_t)row * D + k0 + c]);
            As[c + 0][r] = v.x;
            As[c + 1][r] = v.y;
            As[c + 2][r] = v.z;
            As[c + 3][r] = v.w;
        }
        #pragma unroll
        for (int i = 0; i < 2; i++) {
            int f = tid + i * 256;
            int r = f >> 5;
            int c = (f & 31) * 4;
            *reinterpret_cast<float4*>(&Bs[r][c]) =
                *reinterpret_cast<const float4*>(&B[(size_t)(k0 + r) * D + blockCol + c]);
        }
        __syncthreads();

        #pragma unroll
        for (int k = 0; k < BK; k++) {
            float4 a0 = *reinterpret_cast<const float4*>(&As[k][ty * 4]);
            float4 a1 = *reinterpret_cast<const float4*>(&As[k][ty * 4 + 64]);
            float4 b0 = *reinterpret_cast<const float4*>(&Bs[k][tx * 4]);
            float4 b1 = *reinterpret_cast<const float4*>(&Bs[k][tx * 4 + 64]);
            float a[2][4] = {{a0.x, a0.y, a0.z, a0.w}, {a1.x, a1.y, a1.z, a1.w}};
            float b[2][4] = {{b0.x, b0.y, b0.z, b0.w}, {b1.x, b1.y, b1.z, b1.w}};
            #pragma unroll
            for (int ia = 0; ia < 2; ia++)
                #pragma unroll
                for (int ib = 0; ib < 2; ib++)
                    #pragma unroll
                    for (int i = 0; i < 4; i++)
                        #pragma unroll
                        for (int j = 0; j < 4; j++)
                            acc[ia][ib][i][j] += a[ia][i] * b[ib][j];
        }
        __syncthreads();
    }

    #pragma unroll
    for (int ia = 0; ia < 2; ia++) {
        #pragma unroll
        for (int i = 0; i < 4; i++) {
            int row = blockRow + ia * 64 + ty * 4 + i;
            if (row >= N_NODES) continue;
            #pragma unroll
            for (int ib = 0; ib < 2; ib++) {
                int col = blockCol + ib * 64 + tx * 4;
                __half2 h0 = __float22half2_rn(make_float2(acc[ia][ib][i][0], acc[ia][ib][i][1]));
                __half2 h1 = __float22half2_rn(make_float2(acc[ia][ib][i][2], acc[ia][ib][i][3]));
                uint2 pk = make_uint2(*reinterpret_cast<unsigned*>(&h0),
                                      *reinterpret_cast<unsigned*>(&h1));
                *reinterpret_cast<uint2*>(&g_support[(size_t)row * D + col]) = pk;
            }
        }
    }
}

// ---------------------------------------------------------------------------
// CSR construction
// ---------------------------------------------------------------------------
__global__ __launch_bounds__(256) void zero_count_kernel() {
    int i = blockIdx.x * blockDim.x + threadIdx.x;
    if (i < N_NODES) g_count[i] = 0;
}

__global__ __launch_bounds__(256) void hist_kernel(const int* __restrict__ adj_row, int nE) {
    int e = blockIdx.x * blockDim.x + threadIdx.x;
    if (e < nE) atomicAdd(&g_count[adj_row[e]], 1);
}

__global__ __launch_bounds__(1024) void scan1_kernel() {
    __shared__ int sh[1024];
    int b = blockIdx.x, t = threadIdx.x;
    int base = b * SCAN_CHUNK + t * 4;

    int c[4];
    #pragma unroll
    for (int i = 0; i < 4; i++)
        c[i] = (base + i < N_NODES) ? g_count[base + i] : 0;
    int s = c[0] + c[1] + c[2] + c[3];

    sh[t] = s;
    __syncthreads();
    #pragma unroll
    for (int off = 1; off < 1024; off <<= 1) {
        int v = (t >= off) ? sh[t - off] : 0;
        __syncthreads();
        sh[t] += v;
        __syncthreads();
    }

    int run = (t == 0) ? 0 : sh[t - 1];
    #pragma unroll
    for (int i = 0; i < 4; i++) {
        if (base + i < N_NODES) g_offset[base + i] = run;
        run += c[i];
    }
    if (t == 1023) g_bsum[b] = sh[1023];
}

__global__ __launch_bounds__(1024) void scan2_kernel() {
    __shared__ int s_pre;
    int b = blockIdx.x, t = threadIdx.x;

    if (t < 32) {
        int s = 0;
        for (int i = t; i < b; i += 32) s += g_bsum[i];
        #pragma unroll
        for (int o = 16; o > 0; o >>= 1)
            s += __shfl_down_sync(0xFFFFFFFF, s, o);
        if (t == 0) s_pre = s;
    }
    __syncthreads();
    int pre = s_pre;

    int base = b * SCAN_CHUNK + t * 4;
    #pragma unroll
    for (int i = 0; i < 4; i++) {
        int idx = base + i;
        if (idx < N_NODES) {
            int off = g_offset[idx] + pre;
            g_offset[idx] = off;
            g_cursor[idx] = off;
        }
    }
}

__global__ __launch_bounds__(256) void build_kernel(const int* __restrict__ adj_row,
                                                    const int* __restrict__ adj_col,
                                                    const float* __restrict__ adj_val,
                                                    int nE) {
    int e = blockIdx.x * blockDim.x + threadIdx.x;
    if (e >= nE) return;
    int r = adj_row[e];
    int pos = atomicAdd(&g_cursor[r], 1);
    g_csr[pos] = make_uint2((unsigned)adj_col[e], __float_as_uint(adj_val[e]));
}

// ---------------------------------------------------------------------------
// CSR SpMM: warp per row, lane owns 8 halves (one 16B load per edge),
// 8-deep unrolled gather (8 outstanding LDG.128/lane), fp32 accumulate,
// two accumulator banks, bias fused.
// ---------------------------------------------------------------------------
__device__ __forceinline__ void fma_halves(float acc[8], uint4 x, float v) {
    __half2* h = reinterpret_cast<__half2*>(&x);
    #pragma unroll
    for (int i = 0; i < 4; i++) {
        float2 f = __half22float2(h[i]);
        acc[i * 2 + 0] += f.x * v;
        acc[i * 2 + 1] += f.y * v;
    }
}

__global__ __launch_bounds__(256) void spmm_kernel(const float* __restrict__ bias,
                                                   float* __restrict__ out) {
    int gtid = blockIdx.x * blockDim.x + threadIdx.x;
    int r    = gtid >> 5;
    int lane = gtid & 31;
    if (r >= N_NODES) return;

    int start = g_offset[r];
    int end   = start + g_count[r];

    float accA[8] = {};
    float accB[8] = {};

    int p = start;
    // 8-deep unroll: 8 outstanding 16B gathers per lane
    for (; p + 7 < end; p += 8) {
        uint2 e0 = g_csr[p + 0];
        uint2 e1 = g_csr[p + 1];
        uint2 e2 = g_csr[p + 2];
        uint2 e3 = g_csr[p + 3];
        uint2 e4 = g_csr[p + 4];
        uint2 e5 = g_csr[p + 5];
        uint2 e6 = g_csr[p + 6];
        uint2 e7 = g_csr[p + 7];
        uint4 x0 = *(reinterpret_cast<const uint4*>(g_support + (size_t)e0.x * D) + lane);
        uint4 x1 = *(reinterpret_cast<const uint4*>(g_support + (size_t)e1.x * D) + lane);
        uint4 x2 = *(reinterpret_cast<const uint4*>(g_support + (size_t)e2.x * D) + lane);
        uint4 x3 = *(reinterpret_cast<const uint4*>(g_support + (size_t)e3.x * D) + lane);
        uint4 x4 = *(reinterpret_cast<const uint4*>(g_support + (size_t)e4.x * D) + lane);
        uint4 x5 = *(reinterpret_cast<const uint4*>(g_support + (size_t)e5.x * D) + lane);
        uint4 x6 = *(reinterpret_cast<const uint4*>(g_support + (size_t)e6.x * D) + lane);
        uint4 x7 = *(reinterpret_cast<const uint4*>(g_support + (size_t)e7.x * D) + lane);
        fma_halves(accA, x0, __uint_as_float(e0.y));
        fma_halves(accB, x1, __uint_as_float(e1.y));
        fma_halves(accA, x2, __uint_as_float(e2.y));
        fma_halves(accB, x3, __uint_as_float(e3.y));
        fma_halves(accA, x4, __uint_as_float(e4.y));
        fma_halves(accB, x5, __uint_as_float(e5.y));
        fma_halves(accA, x6, __uint_as_float(e6.y));
        fma_halves(accB, x7, __uint_as_float(e7.y));
    }
    // 2-deep remainder
    for (; p + 1 < end; p += 2) {
        uint2 e0 = g_csr[p + 0];
        uint2 e1 = g_csr[p + 1];
        uint4 x0 = *(reinterpret_cast<const uint4*>(g_support + (size_t)e0.x * D) + lane);
        uint4 x1 = *(reinterpret_cast<const uint4*>(g_support + (size_t)e1.x * D) + lane);
        fma_halves(accA, x0, __uint_as_float(e0.y));
        fma_halves(accB, x1, __uint_as_float(e1.y));
    }
    if (p < end) {
        uint2 e = g_csr[p];
        uint4 x = *(reinterpret_cast<const uint4*>(g_support + (size_t)e.x * D) + lane);
        fma_halves(accA, x, __uint_as_float(e.y));
    }

    const float4* bp = reinterpret_cast<const float4*>(bias) + lane * 2;
    float4 b0 = bp[0], b1 = bp[1];
    float o0 = accA[0] + accB[0] + b0.x;
    float o1 = accA[1] + accB[1] + b0.y;
    float o2 = accA[2] + accB[2] + b0.z;
    float o3 = accA[3] + accB[3] + b0.w;
    float o4 = accA[4] + accB[4] + b1.x;
    float o5 = accA[5] + accB[5] + b1.y;
    float o6 = accA[6] + accB[6] + b1.z;
    float o7 = accA[7] + accB[7] + b1.w;

    float4* dst = reinterpret_cast<float4*>(out + (size_t)r * D) + lane * 2;
    dst[0] = make_float4(o0, o1, o2, o3);
    dst[1] = make_float4(o4, o5, o6, o7);
}

// ---------------------------------------------------------------------------
// Launch
// ---------------------------------------------------------------------------
extern "C" void kernel_launch(void* const* d_in, const int* in_sizes, int n_in,
                              void* d_out, int out_size) {
    const float* X    = (const float*)d_in[0];
    const int*   arow = (const int*)  d_in[1];
    const int*   acol = (const int*)  d_in[2];
    const float* aval = (const float*)d_in[3];
    const float* W    = (const float*)d_in[4];
    const float* bias = (const float*)d_in[5];
    float*       out  = (float*)d_out;

    int nE = in_sizes[1];
    if (nE > MAX_E) nE = MAX_E;

    // 1) support = X @ W  (fp16 store)
    dim3 gemm_grid(D / 128, (N_NODES + 127) / 128);
    gemm_kernel<<<gemm_grid, 256>>>(X, W);

    // 2) CSR build (parallel scan)
    zero_count_kernel<<<(N_NODES + 255) / 256, 256>>>();
    hist_kernel<<<(nE + 255) / 256, 256>>>(arow, nE);
    scan1_kernel<<<SCAN_BLOCKS, 1024>>>();
    scan2_kernel<<<SCAN_BLOCKS, 1024>>>();
    build_kernel<<<(nE + 255) / 256, 256>>>(arow, acol, aval, nE);

    // 3) SpMM (warp per row), bias fused
    long long total_threads = (long long)N_NODES * 32;
    int nblk = (int)((total_threads + 255) / 256);
    spmm_kernel<<<nblk, 256>>>(bias, out);
}

// round 8
// speedup vs baseline: 1.4138x; 1.0249x over previous
#include <cuda_runtime.h>
#include <cuda_fp16.h>
#include <mma.h>
#include <cstdint>

using namespace nvcuda;

#define N_NODES 100000
#define D 256
#define MAX_E 3200000

#define SCAN_CHUNK 4096
#define SCAN_BLOCKS ((N_NODES + SCAN_CHUNK - 1) / SCAN_CHUNK)   // 25

// Static device scratch (allocation-free rule)
__device__ __half g_support[(size_t)N_NODES * D];   // X @ W in fp16 (51.2 MB)
__device__ int    g_count [N_NODES];
__device__ int    g_offset[N_NODES];
__device__ int    g_cursor[N_NODES];
__device__ int    g_bsum  [SCAN_BLOCKS];
__device__ uint2  g_csr   [MAX_E];                  // {col, val bits}

// ---------------------------------------------------------------------------
// Kernel 1: tf32 tensor-core GEMM  support = X[100000,256] @ W[256,256]
// 128x128 tile, BK=16, 256 threads = 8 warps (4m x 2n), warp tile 32x64.
// fp32 accumulate, fp16 store. A/B converted to tf32 at smem-store time.
// ---------------------------------------------------------------------------
__global__ __launch_bounds__(256) void gemm_kernel(const float* __restrict__ A,
                                                   const float* __restrict__ B) {
    __shared__ union {
        struct {
            float As[128][16];   // row-major, ld 16
            float Bs[16][128];   // row-major (k x n), ld 128
        } t;
        float staging[128][64];  // epilogue staging, ld 64
    } sh;

    int tid  = threadIdx.x;
    int wid  = tid >> 5;
    int warp_m = wid >> 1;       // 0..3
    int warp_n = wid & 1;        // 0..1
    int blockRow = blockIdx.y * 128;
    int blockCol = blockIdx.x * 128;

    wmma::fragment<wmma::accumulator, 16, 16, 8, float> acc[2][4];
    #pragma unroll
    for (int i = 0; i < 2; i++)
        #pragma unroll
        for (int j = 0; j < 4; j++)
            wmma::fill_fragment(acc[i][j], 0.0f);

    for (int k0 = 0; k0 < D; k0 += 16) {
        // A tile 128x16 (512 float4, 2 per thread), convert to tf32
        #pragma unroll
        for (int i = 0; i < 2; i++) {
            int f = tid + i * 256;
            int r = f >> 2;
            int c = (f & 3) * 4;
            int row = blockRow + r;
            float4 v = make_float4(0.f, 0.f, 0.f, 0.f);
            if (row < N_NODES)
                v = *reinterpret_cast<const float4*>(&A[(size_t)row * D + k0 + c]);
            sh.t.As[r][c + 0] = wmma::__float_to_tf32(v.x);
            sh.t.As[r][c + 1] = wmma::__float_to_tf32(v.y);
            sh.t.As[r][c + 2] = wmma::__float_to_tf32(v.z);
            sh.t.As[r][c + 3] = wmma::__float_to_tf32(v.w);
        }
        // B tile 16x128 (512 float4, 2 per thread), convert to tf32
        #pragma unroll
        for (int i = 0; i < 2; i++) {
            int f = tid + i * 256;
            int r = f >> 5;
            int c = (f & 31) * 4;
            float4 v = *reinterpret_cast<const float4*>(&B[(size_t)(k0 + r) * D + blockCol + c]);
            sh.t.Bs[r][c + 0] = wmma::__float_to_tf32(v.x);
            sh.t.Bs[r][c + 1] = wmma::__float_to_tf32(v.y);
            sh.t.Bs[r][c + 2] = wmma::__float_to_tf32(v.z);
            sh.t.Bs[r][c + 3] = wmma::__float_to_tf32(v.w);
        }
        __syncthreads();

        #pragma unroll
        for (int kk = 0; kk < 16; kk += 8) {
            wmma::fragment<wmma::matrix_a, 16, 16, 8, wmma::precision::tf32, wmma::row_major> a[2];
            wmma::load_matrix_sync(a[0], &sh.t.As[warp_m * 32][kk], 16);
            wmma::load_matrix_sync(a[1], &sh.t.As[warp_m * 32 + 16][kk], 16);
            #pragma unroll
            for (int j = 0; j < 4; j++) {
                wmma::fragment<wmma::matrix_b, 16, 16, 8, wmma::precision::tf32, wmma::row_major> b;
                wmma::load_matrix_sync(b, &sh.t.Bs[kk][warp_n * 64 + j * 16], 128);
                wmma::mma_sync(acc[0][j], a[0], b, acc[0][j]);
                wmma::mma_sync(acc[1][j], a[1], b, acc[1][j]);
            }
        }
        __syncthreads();
    }

    // Epilogue: two phases (n-half 0 then 1) through 128x64 smem staging.
    #pragma unroll
    for (int phase = 0; phase < 2; phase++) {
        __syncthreads();
        if (warp_n == phase) {
            #pragma unroll
            for (int i = 0; i < 2; i++)
                #pragma unroll
                for (int j = 0; j < 4; j++)
                    wmma::store_matrix_sync(&sh.staging[warp_m * 32 + i * 16][j * 16],
                                            acc[i][j], 64, wmma::mem_row_major);
        }
        __syncthreads();
        // 128x64 floats = 2048 float4, 8 per thread; convert to fp16 and store.
        #pragma unroll
        for (int it = 0; it < 8; it++) {
            int f = tid + it * 256;
            int r  = f >> 4;            // 0..127
            int c4 = (f & 15) * 4;      // 0..60
            int row = blockRow + r;
            if (row < N_NODES) {
                float4 v = *reinterpret_cast<const float4*>(&sh.staging[r][c4]);
                __half2 h0 = __float22half2_rn(make_float2(v.x, v.y));
                __half2 h1 = __float22half2_rn(make_float2(v.z, v.w));
                uint2 pk = make_uint2(*reinterpret_cast<unsigned*>(&h0),
                                      *reinterpret_cast<unsigned*>(&h1));
                *reinterpret_cast<uint2*>(&g_support[(size_t)row * D + blockCol + phase * 64 + c4]) = pk;
            }
        }
    }
}

// ---------------------------------------------------------------------------
// CSR construction
// ---------------------------------------------------------------------------
__global__ __launch_bounds__(256) void zero_count_kernel() {
    int i = blockIdx.x * blockDim.x + threadIdx.x;
    if (i < N_NODES) g_count[i] = 0;
}

__global__ __launch_bounds__(256) void hist_kernel(const int* __restrict__ adj_row, int nE) {
    int e = blockIdx.x * blockDim.x + threadIdx.x;
    if (e < nE) atomicAdd(&g_count[adj_row[e]], 1);
}

__global__ __launch_bounds__(1024) void scan1_kernel() {
    __shared__ int sh[1024];
    int b = blockIdx.x, t = threadIdx.x;
    int base = b * SCAN_CHUNK + t * 4;

    int c[4];
    #pragma unroll
    for (int i = 0; i < 4; i++)
        c[i] = (base + i < N_NODES) ? g_count[base + i] : 0;
    int s = c[0] + c[1] + c[2] + c[3];

    sh[t] = s;
    __syncthreads();
    #pragma unroll
    for (int off = 1; off < 1024; off <<= 1) {
        int v = (t >= off) ? sh[t - off] : 0;
        __syncthreads();
        sh[t] += v;
        __syncthreads();
    }

    int run = (t == 0) ? 0 : sh[t - 1];
    #pragma unroll
    for (int i = 0; i < 4; i++) {
        if (base + i < N_NODES) g_offset[base + i] = run;
        run += c[i];
    }
    if (t == 1023) g_bsum[b] = sh[1023];
}

__global__ __launch_bounds__(1024) void scan2_kernel() {
    __shared__ int s_pre;
    int b = blockIdx.x, t = threadIdx.x;

    if (t < 32) {
        int s = 0;
        for (int i = t; i < b; i += 32) s += g_bsum[i];
        #pragma unroll
        for (int o = 16; o > 0; o >>= 1)
            s += __shfl_down_sync(0xFFFFFFFF, s, o);
        if (t == 0) s_pre = s;
    }
    __syncthreads();
    int pre = s_pre;

    int base = b * SCAN_CHUNK + t * 4;
    #pragma unroll
    for (int i = 0; i < 4; i++) {
        int idx = base + i;
        if (idx < N_NODES) {
            int off = g_offset[idx] + pre;
            g_offset[idx] = off;
            g_cursor[idx] = off;
        }
    }
}

__global__ __launch_bounds__(256) void build_kernel(const int* __restrict__ adj_row,
                                                    const int* __restrict__ adj_col,
                                                    const float* __restrict__ adj_val,
                                                    int nE) {
    int e = blockIdx.x * blockDim.x + threadIdx.x;
    if (e >= nE) return;
    int r = adj_row[e];
    int pos = atomicAdd(&g_cursor[r], 1);
    g_csr[pos] = make_uint2((unsigned)adj_col[e], __float_as_uint(adj_val[e]));
}

// ---------------------------------------------------------------------------
// CSR SpMM: warp per row, lane owns 8 halves (one 16B load per edge),
// 8-deep unrolled gather, fp32 accumulate, two accumulator banks, bias fused.
// ---------------------------------------------------------------------------
__device__ __forceinline__ void fma_halves(float acc[8], uint4 x, float v) {
    __half2* h = reinterpret_cast<__half2*>(&x);
    #pragma unroll
    for (int i = 0; i < 4; i++) {
        float2 f = __half22float2(h[i]);
        acc[i * 2 + 0] += f.x * v;
        acc[i * 2 + 1] += f.y * v;
    }
}

__global__ __launch_bounds__(256) void spmm_kernel(const float* __restrict__ bias,
                                                   float* __restrict__ out) {
    int gtid = blockIdx.x * blockDim.x + threadIdx.x;
    int r    = gtid >> 5;
    int lane = gtid & 31;
    if (r >= N_NODES) return;

    int start = g_offset[r];
    int end   = start + g_count[r];

    float accA[8] = {};
    float accB[8] = {};

    int p = start;
    for (; p + 7 < end; p += 8) {
        uint2 e0 = g_csr[p + 0];
        uint2 e1 = g_csr[p + 1];
        uint2 e2 = g_csr[p + 2];
        uint2 e3 = g_csr[p + 3];
        uint2 e4 = g_csr[p + 4];
        uint2 e5 = g_csr[p + 5];
        uint2 e6 = g_csr[p + 6];
        uint2 e7 = g_csr[p + 7];
        uint4 x0 = *(reinterpret_cast<const uint4*>(g_support + (size_t)e0.x * D) + lane);
        uint4 x1 = *(reinterpret_cast<const uint4*>(g_support + (size_t)e1.x * D) + lane);
        uint4 x2 = *(reinterpret_cast<const uint4*>(g_support + (size_t)e2.x * D) + lane);
        uint4 x3 = *(reinterpret_cast<const uint4*>(g_support + (size_t)e3.x * D) + lane);
        uint4 x4 = *(reinterpret_cast<const uint4*>(g_support + (size_t)e4.x * D) + lane);
        uint4 x5 = *(reinterpret_cast<const uint4*>(g_support + (size_t)e5.x * D) + lane);
        uint4 x6 = *(reinterpret_cast<const uint4*>(g_support + (size_t)e6.x * D) + lane);
        uint4 x7 = *(reinterpret_cast<const uint4*>(g_support + (size_t)e7.x * D) + lane);
        fma_halves(accA, x0, __uint_as_float(e0.y));
        fma_halves(accB, x1, __uint_as_float(e1.y));
        fma_halves(accA, x2, __uint_as_float(e2.y));
        fma_halves(accB, x3, __uint_as_float(e3.y));
        fma_halves(accA, x4, __uint_as_float(e4.y));
        fma_halves(accB, x5, __uint_as_float(e5.y));
        fma_halves(accA, x6, __uint_as_float(e6.y));
        fma_halves(accB, x7, __uint_as_float(e7.y));
    }
    for (; p + 1 < end; p += 2) {
        uint2 e0 = g_csr[p + 0];
        uint2 e1 = g_csr[p + 1];
        uint4 x0 = *(reinterpret_cast<const uint4*>(g_support + (size_t)e0.x * D) + lane);
        uint4 x1 = *(reinterpret_cast<const uint4*>(g_support + (size_t)e1.x * D) + lane);
        fma_halves(accA, x0, __uint_as_float(e0.y));
        fma_halves(accB, x1, __uint_as_float(e1.y));
    }
    if (p < end) {
        uint2 e = g_csr[p];
        uint4 x = *(reinterpret_cast<const uint4*>(g_support + (size_t)e.x * D) + lane);
        fma_halves(accA, x, __uint_as_float(e.y));
    }

    const float4* bp = reinterpret_cast<const float4*>(bias) + lane * 2;
    float4 b0 = bp[0], b1 = bp[1];
    float o0 = accA[0] + accB[0] + b0.x;
    float o1 = accA[1] + accB[1] + b0.y;
    float o2 = accA[2] + accB[2] + b0.z;
    float o3 = accA[3] + accB[3] + b0.w;
    float o4 = accA[4] + accB[4] + b1.x;
    float o5 = accA[5] + accB[5] + b1.y;
    float o6 = accA[6] + accB[6] + b1.z;
    float o7 = accA[7] + accB[7] + b1.w;

    float4* dst = reinterpret_cast<float4*>(out + (size_t)r * D) + lane * 2;
    dst[0] = make_float4(o0, o1, o2, o3);
    dst[1] = make_float4(o4, o5, o6, o7);
}

// ---------------------------------------------------------------------------
// Launch
// ---------------------------------------------------------------------------
extern "C" void kernel_launch(void* const* d_in, const int* in_sizes, int n_in,
                              void* d_out, int out_size) {
    const float* X    = (const float*)d_in[0];
    const int*   arow = (const int*)  d_in[1];
    const int*   acol = (const int*)  d_in[2];
    const float* aval = (const float*)d_in[3];
    const float* W    = (const float*)d_in[4];
    const float* bias = (const float*)d_in[5];
    float*       out  = (float*)d_out;

    int nE = in_sizes[1];
    if (nE > MAX_E) nE = MAX_E;

    // 1) support = X @ W  (tf32 tensor cores, fp16 store)
    dim3 gemm_grid(D / 128, (N_NODES + 127) / 128);
    gemm_kernel<<<gemm_grid, 256>>>(X, W);

    // 2) CSR build (parallel scan)
    zero_count_kernel<<<(N_NODES + 255) / 256, 256>>>();
    hist_kernel<<<(nE + 255) / 256, 256>>>(arow, nE);
    scan1_kernel<<<SCAN_BLOCKS, 1024>>>();
    scan2_kernel<<<SCAN_BLOCKS, 1024>>>();
    build_kernel<<<(nE + 255) / 256, 256>>>(arow, acol, aval, nE);

    // 3) SpMM (warp per row), bias fused
    long long total_threads = (long long)N_NODES * 32;
    int nblk = (int)((total_threads + 255) / 256);
    spmm_kernel<<<nblk, 256>>>(bias, out);
}

// round 9
// speedup vs baseline: 1.4617x; 1.0339x over previous
#include <cuda_runtime.h>
#include <cuda_fp16.h>
#include <mma.h>
#include <cstdint>

using namespace nvcuda;

#define N_NODES 100000
#define D 256
#define MAX_E 3200000

#define SCAN_CHUNK 4096
#define SCAN_BLOCKS ((N_NODES + SCAN_CHUNK - 1) / SCAN_CHUNK)   // 25

// Static device scratch (allocation-free rule)
__device__ __half g_support[(size_t)N_NODES * D];   // X @ W in fp16 (51.2 MB)
__device__ int    g_count [N_NODES];
__device__ int    g_offset[N_NODES];
__device__ int    g_cursor[N_NODES];
__device__ int    g_bsum  [SCAN_BLOCKS];
__device__ uint2  g_csr   [MAX_E];                  // {col, val bits}

// ---------------------------------------------------------------------------
// Kernel 1: tf32 tensor-core GEMM  support = X[100000,256] @ W[256,256]
// 128x128 tile, BK=32, 256 threads = 8 warps (4m x 2n), warp tile 32x64.
// Conflict-free smem: all row strides ≡ 4 (mod 32) floats.
// fp32 accumulate, fp16 store via padded staging.
// ---------------------------------------------------------------------------
#define AS_LD 36     // 36 mod 32 = 4  -> 8-row start-bank cycle, conflict-free
#define BS_LD 132    // 132 mod 32 = 4
#define ST_LD 68     // 68 mod 32 = 4

__global__ __launch_bounds__(256) void gemm_kernel(const float* __restrict__ A,
                                                   const float* __restrict__ B) {
    __shared__ union {
        struct {
            float As[128][AS_LD];    // 18432 B
            float Bs[32][BS_LD];     // 16896 B
        } t;
        float staging[128][ST_LD];   // 34816 B
    } sh;

    int tid  = threadIdx.x;
    int wid  = tid >> 5;
    int warp_m = wid >> 1;       // 0..3
    int warp_n = wid & 1;        // 0..1
    int blockRow = blockIdx.y * 128;
    int blockCol = blockIdx.x * 128;

    wmma::fragment<wmma::accumulator, 16, 16, 8, float> acc[2][4];
    #pragma unroll
    for (int i = 0; i < 2; i++)
        #pragma unroll
        for (int j = 0; j < 4; j++)
            wmma::fill_fragment(acc[i][j], 0.0f);

    for (int k0 = 0; k0 < D; k0 += 32) {
        // A tile 128x32 = 1024 float4, 4 per thread; convert to tf32
        #pragma unroll
        for (int i = 0; i < 4; i++) {
            int f = tid + i * 256;          // 0..1023
            int r = f >> 3;                 // 0..127
            int c = (f & 7) * 4;            // 0..28
            int row = blockRow + r;
            float4 v = make_float4(0.f, 0.f, 0.f, 0.f);
            if (row < N_NODES)
                v = *reinterpret_cast<const float4*>(&A[(size_t)row * D + k0 + c]);
            sh.t.As[r][c + 0] = wmma::__float_to_tf32(v.x);
            sh.t.As[r][c + 1] = wmma::__float_to_tf32(v.y);
            sh.t.As[r][c + 2] = wmma::__float_to_tf32(v.z);
            sh.t.As[r][c + 3] = wmma::__float_to_tf32(v.w);
        }
        // B tile 32x128 = 1024 float4, 4 per thread; convert to tf32
        #pragma unroll
        for (int i = 0; i < 4; i++) {
            int f = tid + i * 256;
            int r = f >> 5;                 // 0..31
            int c = (f & 31) * 4;           // 0..124
            float4 v = *reinterpret_cast<const float4*>(&B[(size_t)(k0 + r) * D + blockCol + c]);
            sh.t.Bs[r][c + 0] = wmma::__float_to_tf32(v.x);
            sh.t.Bs[r][c + 1] = wmma::__float_to_tf32(v.y);
            sh.t.Bs[r][c + 2] = wmma::__float_to_tf32(v.z);
            sh.t.Bs[r][c + 3] = wmma::__float_to_tf32(v.w);
        }
        __syncthreads();

        #pragma unroll
        for (int kk = 0; kk < 32; kk += 8) {
            wmma::fragment<wmma::matrix_a, 16, 16, 8, wmma::precision::tf32, wmma::row_major> a[2];
            wmma::load_matrix_sync(a[0], &sh.t.As[warp_m * 32][kk], AS_LD);
            wmma::load_matrix_sync(a[1], &sh.t.As[warp_m * 32 + 16][kk], AS_LD);
            #pragma unroll
            for (int j = 0; j < 4; j++) {
                wmma::fragment<wmma::matrix_b, 16, 16, 8, wmma::precision::tf32, wmma::row_major> b;
                wmma::load_matrix_sync(b, &sh.t.Bs[kk][warp_n * 64 + j * 16], BS_LD);
                wmma::mma_sync(acc[0][j], a[0], b, acc[0][j]);
                wmma::mma_sync(acc[1][j], a[1], b, acc[1][j]);
            }
        }
        __syncthreads();
    }

    // Epilogue: two phases (n-half 0 then 1) through padded staging.
    #pragma unroll
    for (int phase = 0; phase < 2; phase++) {
        __syncthreads();
        if (warp_n == phase) {
            #pragma unroll
            for (int i = 0; i < 2; i++)
                #pragma unroll
                for (int j = 0; j < 4; j++)
                    wmma::store_matrix_sync(&sh.staging[warp_m * 32 + i * 16][j * 16],
                                            acc[i][j], ST_LD, wmma::mem_row_major);
        }
        __syncthreads();
        // 128x64 floats = 2048 float4, 8 per thread; fp16 pack + store.
        #pragma unroll
        for (int it = 0; it < 8; it++) {
            int f = tid + it * 256;
            int r  = f >> 4;            // 0..127
            int c4 = (f & 15) * 4;      // 0..60
            int row = blockRow + r;
            if (row < N_NODES) {
                float4 v = *reinterpret_cast<const float4*>(&sh.staging[r][c4]);
                __half2 h0 = __float22half2_rn(make_float2(v.x, v.y));
                __half2 h1 = __float22half2_rn(make_float2(v.z, v.w));
                uint2 pk = make_uint2(*reinterpret_cast<unsigned*>(&h0),
                                      *reinterpret_cast<unsigned*>(&h1));
                *reinterpret_cast<uint2*>(&g_support[(size_t)row * D + blockCol + phase * 64 + c4]) = pk;
            }
        }
    }
}

// ---------------------------------------------------------------------------
// CSR construction
// ---------------------------------------------------------------------------
__global__ __launch_bounds__(256) void zero_count_kernel() {
    int i = blockIdx.x * blockDim.x + threadIdx.x;
    if (i < N_NODES) g_count[i] = 0;
}

__global__ __launch_bounds__(256) void hist_kernel(const int* __restrict__ adj_row, int nE) {
    int e = blockIdx.x * blockDim.x + threadIdx.x;
    if (e < nE) atomicAdd(&g_count[adj_row[e]], 1);
}

__global__ __launch_bounds__(1024) void scan1_kernel() {
    __shared__ int sh[1024];
    int b = blockIdx.x, t = threadIdx.x;
    int base = b * SCAN_CHUNK + t * 4;

    int c[4];
    #pragma unroll
    for (int i = 0; i < 4; i++)
        c[i] = (base + i < N_NODES) ? g_count[base + i] : 0;
    int s = c[0] + c[1] + c[2] + c[3];

    sh[t] = s;
    __syncthreads();
    #pragma unroll
    for (int off = 1; off < 1024; off <<= 1) {
        int v = (t >= off) ? sh[t - off] : 0;
        __syncthreads();
        sh[t] += v;
        __syncthreads();
    }

    int run = (t == 0) ? 0 : sh[t - 1];
    #pragma unroll
    for (int i = 0; i < 4; i++) {
        if (base + i < N_NODES) g_offset[base + i] = run;
        run += c[i];
    }
    if (t == 1023) g_bsum[b] = sh[1023];
}

__global__ __launch_bounds__(1024) void scan2_kernel() {
    __shared__ int s_pre;
    int b = blockIdx.x, t = threadIdx.x;

    if (t < 32) {
        int s = 0;
        for (int i = t; i < b; i += 32) s += g_bsum[i];
        #pragma unroll
        for (int o = 16; o > 0; o >>= 1)
            s += __shfl_down_sync(0xFFFFFFFF, s, o);
        if (t == 0) s_pre = s;
    }
    __syncthreads();
    int pre = s_pre;

    int base = b * SCAN_CHUNK + t * 4;
    #pragma unroll
    for (int i = 0; i < 4; i++) {
        int idx = base + i;
        if (idx < N_NODES) {
            int off = g_offset[idx] + pre;
            g_offset[idx] = off;
            g_cursor[idx] = off;
        }
    }
}

__global__ __launch_bounds__(256) void build_kernel(const int* __restrict__ adj_row,
                                                    const int* __restrict__ adj_col,
                                                    const float* __restrict__ adj_val,
                                                    int nE) {
    int e = blockIdx.x * blockDim.x + threadIdx.x;
    if (e >= nE) return;
    int r = adj_row[e];
    int pos = atomicAdd(&g_cursor[r], 1);
    g_csr[pos] = make_uint2((unsigned)adj_col[e], __float_as_uint(adj_val[e]));
}

// ---------------------------------------------------------------------------
// CSR SpMM: warp per row, lane owns 8 halves (one 16B load per edge),
// 8-deep unrolled gather, fp32 accumulate, two accumulator banks, bias fused.
// ---------------------------------------------------------------------------
__device__ __forceinline__ void fma_halves(float acc[8], uint4 x, float v) {
    __half2* h = reinterpret_cast<__half2*>(&x);
    #pragma unroll
    for (int i = 0; i < 4; i++) {
        float2 f = __half22float2(h[i]);
        acc[i * 2 + 0] += f.x * v;
        acc[i * 2 + 1] += f.y * v;
    }
}

__global__ __launch_bounds__(256) void spmm_kernel(const float* __restrict__ bias,
                                                   float* __restrict__ out) {
    int gtid = blockIdx.x * blockDim.x + threadIdx.x;
    int r    = gtid >> 5;
    int lane = gtid & 31;
    if (r >= N_NODES) return;

    int start = g_offset[r];
    int end   = start + g_count[r];

    float accA[8] = {};
    float accB[8] = {};

    int p = start;
    for (; p + 7 < end; p += 8) {
        uint2 e0 = g_csr[p + 0];
        uint2 e1 = g_csr[p + 1];
        uint2 e2 = g_csr[p + 2];
        uint2 e3 = g_csr[p + 3];
        uint2 e4 = g_csr[p + 4];
        uint2 e5 = g_csr[p + 5];
        uint2 e6 = g_csr[p + 6];
        uint2 e7 = g_csr[p + 7];
        uint4 x0 = *(reinterpret_cast<const uint4*>(g_support + (size_t)e0.x * D) + lane);
        uint4 x1 = *(reinterpret_cast<const uint4*>(g_support + (size_t)e1.x * D) + lane);
        uint4 x2 = *(reinterpret_cast<const uint4*>(g_support + (size_t)e2.x * D) + lane);
        uint4 x3 = *(reinterpret_cast<const uint4*>(g_support + (size_t)e3.x * D) + lane);
        uint4 x4 = *(reinterpret_cast<const uint4*>(g_support + (size_t)e4.x * D) + lane);
        uint4 x5 = *(reinterpret_cast<const uint4*>(g_support + (size_t)e5.x * D) + lane);
        uint4 x6 = *(reinterpret_cast<const uint4*>(g_support + (size_t)e6.x * D) + lane);
        uint4 x7 = *(reinterpret_cast<const uint4*>(g_support + (size_t)e7.x * D) + lane);
        fma_halves(accA, x0, __uint_as_float(e0.y));
        fma_halves(accB, x1, __uint_as_float(e1.y));
        fma_halves(accA, x2, __uint_as_float(e2.y));
        fma_halves(accB, x3, __uint_as_float(e3.y));
        fma_halves(accA, x4, __uint_as_float(e4.y));
        fma_halves(accB, x5, __uint_as_float(e5.y));
        fma_halves(accA, x6, __uint_as_float(e6.y));
        fma_halves(accB, x7, __uint_as_float(e7.y));
    }
    for (; p + 1 < end; p += 2) {
        uint2 e0 = g_csr[p + 0];
        uint2 e1 = g_csr[p + 1];
        uint4 x0 = *(reinterpret_cast<const uint4*>(g_support + (size_t)e0.x * D) + lane);
        uint4 x1 = *(reinterpret_cast<const uint4*>(g_support + (size_t)e1.x * D) + lane);
        fma_halves(accA, x0, __uint_as_float(e0.y));
        fma_halves(accB, x1, __uint_as_float(e1.y));
    }
    if (p < end) {
        uint2 e = g_csr[p];
        uint4 x = *(reinterpret_cast<const uint4*>(g_support + (size_t)e.x * D) + lane);
        fma_halves(accA, x, __uint_as_float(e.y));
    }

    const float4* bp = reinterpret_cast<const float4*>(bias) + lane * 2;
    float4 b0 = bp[0], b1 = bp[1];
    float o0 = accA[0] + accB[0] + b0.x;
    float o1 = accA[1] + accB[1] + b0.y;
    float o2 = accA[2] + accB[2] + b0.z;
    float o3 = accA[3] + accB[3] + b0.w;
    float o4 = accA[4] + accB[4] + b1.x;
    float o5 = accA[5] + accB[5] + b1.y;
    float o6 = accA[6] + accB[6] + b1.z;
    float o7 = accA[7] + accB[7] + b1.w;

    float4* dst = reinterpret_cast<float4*>(out + (size_t)r * D) + lane * 2;
    dst[0] = make_float4(o0, o1, o2, o3);
    dst[1] = make_float4(o4, o5, o6, o7);
}

// ---------------------------------------------------------------------------
// Launch
// ---------------------------------------------------------------------------
extern "C" void kernel_launch(void* const* d_in, const int* in_sizes, int n_in,
                              void* d_out, int out_size) {
    const float* X    = (const float*)d_in[0];
    const int*   arow = (const int*)  d_in[1];
    const int*   acol = (const int*)  d_in[2];
    const float* aval = (const float*)d_in[3];
    const float* W    = (const float*)d_in[4];
    const float* bias = (const float*)d_in[5];
    float*       out  = (float*)d_out;

    int nE = in_sizes[1];
    if (nE > MAX_E) nE = MAX_E;

    // 1) support = X @ W  (tf32 tensor cores, conflict-free smem, fp16 store)
    dim3 gemm_grid(D / 128, (N_NODES + 127) / 128);
    gemm_kernel<<<gemm_grid, 256>>>(X, W);

    // 2) CSR build (parallel scan)
    zero_count_kernel<<<(N_NODES + 255) / 256, 256>>>();
    hist_kernel<<<(nE + 255) / 256, 256>>>(arow, nE);
    scan1_kernel<<<SCAN_BLOCKS, 1024>>>();
    scan2_kernel<<<SCAN_BLOCKS, 1024>>>();
    build_kernel<<<(nE + 255) / 256, 256>>>(arow, acol, aval, nE);

    // 3) SpMM (warp per row), bias fused
    long long total_threads = (long long)N_NODES * 32;
    int nblk = (int)((total_threads + 255) / 256);
    spmm_kernel<<<nblk, 256>>>(bias, out);
}

// round 10
// speedup vs baseline: 2.1910x; 1.4989x over previous
#include <cuda_runtime.h>
#include <cuda_fp16.h>
#include <mma.h>
#include <cstdint>

using namespace nvcuda;

#define N_NODES 100000
#define D 256
#define MAX_E 3200000

#define SCAN_CHUNK 4096
#define SCAN_BLOCKS ((N_NODES + SCAN_CHUNK - 1) / SCAN_CHUNK)   // 25

// Static device scratch (allocation-free rule)
__device__ __half g_support[(size_t)N_NODES * D];   // X @ W in fp16 (51.2 MB)
__device__ int    g_count [N_NODES];
__device__ int    g_offset[N_NODES];
__device__ int    g_cursor[N_NODES];
__device__ int    g_bsum  [SCAN_BLOCKS];
__device__ uint2  g_csr   [MAX_E];                  // {col, val bits}

// ---------------------------------------------------------------------------
// Kernel 1: fp16 tensor-core GEMM  support = X[100000,256] @ W[256,256]
// m16n16k16 HMMA (2x the MACs/instr of tf32 k=8 path), fp32 accumulate.
// 128x128 tile, BK=32, 256 threads = 8 warps (4m x 2n), warp tile 32x64.
// As stride 40 halves (80B), Bs stride 136 halves (272B): 8-row start-bank
// cycles cover all 32 banks -> conflict-free ldmatrix.
// ---------------------------------------------------------------------------
#define AS_LD 40     // halves
#define BS_LD 136    // halves
#define ST_LD 68     // floats

__global__ __launch_bounds__(256) void gemm_kernel(const float* __restrict__ A,
                                                   const float* __restrict__ B) {
    __shared__ __align__(32) union {
        struct {
            __half As[128][AS_LD];   // 10240 B
            __half Bs[32][BS_LD];    //  8704 B
        } t;
        float staging[128][ST_LD];   // 34816 B
    } sh;

    int tid  = threadIdx.x;
    int wid  = tid >> 5;
    int warp_m = wid >> 1;       // 0..3
    int warp_n = wid & 1;        // 0..1
    int blockRow = blockIdx.y * 128;
    int blockCol = blockIdx.x * 128;

    wmma::fragment<wmma::accumulator, 16, 16, 16, float> acc[2][4];
    #pragma unroll
    for (int i = 0; i < 2; i++)
        #pragma unroll
        for (int j = 0; j < 4; j++)
            wmma::fill_fragment(acc[i][j], 0.0f);

    for (int k0 = 0; k0 < D; k0 += 32) {
        // A tile 128x32 = 1024 float4-loads worth (4 per thread), fp32->half2
        #pragma unroll
        for (int i = 0; i < 4; i++) {
            int f = tid + i * 256;          // 0..1023
            int r = f >> 3;                 // 0..127
            int c = (f & 7) * 4;            // 0..28
            int row = blockRow + r;
            float4 v = make_float4(0.f, 0.f, 0.f, 0.f);
            if (row < N_NODES)
                v = *reinterpret_cast<const float4*>(&A[(size_t)row * D + k0 + c]);
            __half2 h0 = __float22half2_rn(make_float2(v.x, v.y));
            __half2 h1 = __float22half2_rn(make_float2(v.z, v.w));
            *reinterpret_cast<uint2*>(&sh.t.As[r][c]) =
                make_uint2(*reinterpret_cast<unsigned*>(&h0), *reinterpret_cast<unsigned*>(&h1));
        }
        // B tile 32x128, fp32->half2
        #pragma unroll
        for (int i = 0; i < 4; i++) {
            int f = tid + i * 256;
            int r = f >> 5;                 // 0..31
            int c = (f & 31) * 4;           // 0..124
            float4 v = *reinterpret_cast<const float4*>(&B[(size_t)(k0 + r) * D + blockCol + c]);
            __half2 h0 = __float22half2_rn(make_float2(v.x, v.y));
            __half2 h1 = __float22half2_rn(make_float2(v.z, v.w));
            *reinterpret_cast<uint2*>(&sh.t.Bs[r][c]) =
                make_uint2(*reinterpret_cast<unsigned*>(&h0), *reinterpret_cast<unsigned*>(&h1));
        }
        __syncthreads();

        #pragma unroll
        for (int kk = 0; kk < 32; kk += 16) {
            wmma::fragment<wmma::matrix_a, 16, 16, 16, __half, wmma::row_major> a[2];
            wmma::load_matrix_sync(a[0], &sh.t.As[warp_m * 32][kk], AS_LD);
            wmma::load_matrix_sync(a[1], &sh.t.As[warp_m * 32 + 16][kk], AS_LD);
            #pragma unroll
            for (int j = 0; j < 4; j++) {
                wmma::fragment<wmma::matrix_b, 16, 16, 16, __half, wmma::row_major> b;
                wmma::load_matrix_sync(b, &sh.t.Bs[kk][warp_n * 64 + j * 16], BS_LD);
                wmma::mma_sync(acc[0][j], a[0], b, acc[0][j]);
                wmma::mma_sync(acc[1][j], a[1], b, acc[1][j]);
            }
        }
        __syncthreads();
    }

    // Epilogue: two phases (n-half 0 then 1) through padded float staging.
    #pragma unroll
    for (int phase = 0; phase < 2; phase++) {
        __syncthreads();
        if (warp_n == phase) {
            #pragma unroll
            for (int i = 0; i < 2; i++)
                #pragma unroll
                for (int j = 0; j < 4; j++)
                    wmma::store_matrix_sync(&sh.staging[warp_m * 32 + i * 16][j * 16],
                                            acc[i][j], ST_LD, wmma::mem_row_major);
        }
        __syncthreads();
        // 128x64 floats = 2048 float4, 8 per thread; fp16 pack + store.
        #pragma unroll
        for (int it = 0; it < 8; it++) {
            int f = tid + it * 256;
            int r  = f >> 4;            // 0..127
            int c4 = (f & 15) * 4;      // 0..60
            int row = blockRow + r;
            if (row < N_NODES) {
                float4 v = *reinterpret_cast<const float4*>(&sh.staging[r][c4]);
                __half2 h0 = __float22half2_rn(make_float2(v.x, v.y));
                __half2 h1 = __float22half2_rn(make_float2(v.z, v.w));
                uint2 pk = make_uint2(*reinterpret_cast<unsigned*>(&h0),
                                      *reinterpret_cast<unsigned*>(&h1));
                *reinterpret_cast<uint2*>(&g_support[(size_t)row * D + blockCol + phase * 64 + c4]) = pk;
            }
        }
    }
}

// ---------------------------------------------------------------------------
// CSR construction
// ---------------------------------------------------------------------------
__global__ __launch_bounds__(256) void zero_count_kernel() {
    int i = blockIdx.x * blockDim.x + threadIdx.x;
    if (i < N_NODES) g_count[i] = 0;
}

// 4 edges per thread, vectorized index load.
__global__ __launch_bounds__(256) void hist_kernel(const int* __restrict__ adj_row, int nE) {
    int i = blockIdx.x * blockDim.x + threadIdx.x;
    int e0 = i * 4;
    if (e0 + 3 < nE) {
        int4 r4 = *reinterpret_cast<const int4*>(adj_row + e0);
        atomicAdd(&g_count[r4.x], 1);
        atomicAdd(&g_count[r4.y], 1);
        atomicAdd(&g_count[r4.z], 1);
        atomicAdd(&g_count[r4.w], 1);
    } else {
        for (int e = e0; e < nE; e++) atomicAdd(&g_count[adj_row[e]], 1);
    }
}

__global__ __launch_bounds__(1024) void scan1_kernel() {
    __shared__ int sh[1024];
    int b = blockIdx.x, t = threadIdx.x;
    int base = b * SCAN_CHUNK + t * 4;

    int c[4];
    #pragma unroll
    for (int i = 0; i < 4; i++)
        c[i] = (base + i < N_NODES) ? g_count[base + i] : 0;
    int s = c[0] + c[1] + c[2] + c[3];

    sh[t] = s;
    __syncthreads();
    #pragma unroll
    for (int off = 1; off < 1024; off <<= 1) {
        int v = (t >= off) ? sh[t - off] : 0;
        __syncthreads();
        sh[t] += v;
        __syncthreads();
    }

    int run = (t == 0) ? 0 : sh[t - 1];
    #pragma unroll
    for (int i = 0; i < 4; i++) {
        if (base + i < N_NODES) g_offset[base + i] = run;
        run += c[i];
    }
    if (t == 1023) g_bsum[b] = sh[1023];
}

__global__ __launch_bounds__(1024) void scan2_kernel() {
    __shared__ int s_pre;
    int b = blockIdx.x, t = threadIdx.x;

    if (t < 32) {
        int s = 0;
        for (int i = t; i < b; i += 32) s += g_bsum[i];
        #pragma unroll
        for (int o = 16; o > 0; o >>= 1)
            s += __shfl_down_sync(0xFFFFFFFF, s, o);
        if (t == 0) s_pre = s;
    }
    __syncthreads();
    int pre = s_pre;

    int base = b * SCAN_CHUNK + t * 4;
    #pragma unroll
    for (int i = 0; i < 4; i++) {
        int idx = base + i;
        if (idx < N_NODES) {
            int off = g_offset[idx] + pre;
            g_offset[idx] = off;
            g_cursor[idx] = off;
        }
    }
}

// 4 edges per thread, vectorized loads of row/col/val.
__global__ __launch_bounds__(256) void build_kernel(const int* __restrict__ adj_row,
                                                    const int* __restrict__ adj_col,
                                                    const float* __restrict__ adj_val,
                                                    int nE) {
    int i = blockIdx.x * blockDim.x + threadIdx.x;
    int e0 = i * 4;
    if (e0 + 3 < nE) {
        int4   r4 = *reinterpret_cast<const int4*>(adj_row + e0);
        int4   c4 = *reinterpret_cast<const int4*>(adj_col + e0);
        float4 v4 = *reinterpret_cast<const float4*>(adj_val + e0);
        int p;
        p = atomicAdd(&g_cursor[r4.x], 1); g_csr[p] = make_uint2((unsigned)c4.x, __float_as_uint(v4.x));
        p = atomicAdd(&g_cursor[r4.y], 1); g_csr[p] = make_uint2((unsigned)c4.y, __float_as_uint(v4.y));
        p = atomicAdd(&g_cursor[r4.z], 1); g_csr[p] = make_uint2((unsigned)c4.z, __float_as_uint(v4.z));
        p = atomicAdd(&g_cursor[r4.w], 1); g_csr[p] = make_uint2((unsigned)c4.w, __float_as_uint(v4.w));
    } else {
        for (int e = e0; e < nE; e++) {
            int r = adj_row[e];
            int p = atomicAdd(&g_cursor[r], 1);
            g_csr[p] = make_uint2((unsigned)adj_col[e], __float_as_uint(adj_val[e]));
        }
    }
}

// ---------------------------------------------------------------------------
// CSR SpMM: warp per row, lane owns 8 halves (one 16B load per edge),
// 8-deep unrolled gather, fp32 accumulate, two accumulator banks, bias fused.
// ---------------------------------------------------------------------------
__device__ __forceinline__ void fma_halves(float acc[8], uint4 x, float v) {
    __half2* h = reinterpret_cast<__half2*>(&x);
    #pragma unroll
    for (int i = 0; i < 4; i++) {
        float2 f = __half22float2(h[i]);
        acc[i * 2 + 0] += f.x * v;
        acc[i * 2 + 1] += f.y * v;
    }
}

__global__ __launch_bounds__(256) void spmm_kernel(const float* __restrict__ bias,
                                                   float* __restrict__ out) {
    int gtid = blockIdx.x * blockDim.x + threadIdx.x;
    int r    = gtid >> 5;
    int lane = gtid & 31;
    if (r >= N_NODES) return;

    int start = g_offset[r];
    int end   = start + g_count[r];

    float accA[8] = {};
    float accB[8] = {};

    int p = start;
    for (; p + 7 < end; p += 8) {
        uint2 e0 = g_csr[p + 0];
        uint2 e1 = g_csr[p + 1];
        uint2 e2 = g_csr[p + 2];
        uint2 e3 = g_csr[p + 3];
        uint2 e4 = g_csr[p + 4];
        uint2 e5 = g_csr[p + 5];
        uint2 e6 = g_csr[p + 6];
        uint2 e7 = g_csr[p + 7];
        uint4 x0 = *(reinterpret_cast<const uint4*>(g_support + (size_t)e0.x * D) + lane);
        uint4 x1 = *(reinterpret_cast<const uint4*>(g_support + (size_t)e1.x * D) + lane);
        uint4 x2 = *(reinterpret_cast<const uint4*>(g_support + (size_t)e2.x * D) + lane);
        uint4 x3 = *(reinterpret_cast<const uint4*>(g_support + (size_t)e3.x * D) + lane);
        uint4 x4 = *(reinterpret_cast<const uint4*>(g_support + (size_t)e4.x * D) + lane);
        uint4 x5 = *(reinterpret_cast<const uint4*>(g_support + (size_t)e5.x * D) + lane);
        uint4 x6 = *(reinterpret_cast<const uint4*>(g_support + (size_t)e6.x * D) + lane);
        uint4 x7 = *(reinterpret_cast<const uint4*>(g_support + (size_t)e7.x * D) + lane);
        fma_halves(accA, x0, __uint_as_float(e0.y));
        fma_halves(accB, x1, __uint_as_float(e1.y));
        fma_halves(accA, x2, __uint_as_float(e2.y));
        fma_halves(accB, x3, __uint_as_float(e3.y));
        fma_halves(accA, x4, __uint_as_float(e4.y));
        fma_halves(accB, x5, __uint_as_float(e5.y));
        fma_halves(accA, x6, __uint_as_float(e6.y));
        fma_halves(accB, x7, __uint_as_float(e7.y));
    }
    for (; p + 1 < end; p += 2) {
        uint2 e0 = g_csr[p + 0];
        uint2 e1 = g_csr[p + 1];
        uint4 x0 = *(reinterpret_cast<const uint4*>(g_support + (size_t)e0.x * D) + lane);
        uint4 x1 = *(reinterpret_cast<const uint4*>(g_support + (size_t)e1.x * D) + lane);
        fma_halves(accA, x0, __uint_as_float(e0.y));
        fma_halves(accB, x1, __uint_as_float(e1.y));
    }
    if (p < end) {
        uint2 e = g_csr[p];
        uint4 x = *(reinterpret_cast<const uint4*>(g_support + (size_t)e.x * D) + lane);
        fma_halves(accA, x, __uint_as_float(e.y));
    }

    const float4* bp = reinterpret_cast<const float4*>(bias) + lane * 2;
    float4 b0 = bp[0], b1 = bp[1];
    float o0 = accA[0] + accB[0] + b0.x;
    float o1 = accA[1] + accB[1] + b0.y;
    float o2 = accA[2] + accB[2] + b0.z;
    float o3 = accA[3] + accB[3] + b0.w;
    float o4 = accA[4] + accB[4] + b1.x;
    float o5 = accA[5] + accB[5] + b1.y;
    float o6 = accA[6] + accB[6] + b1.z;
    float o7 = accA[7] + accB[7] + b1.w;

    float4* dst = reinterpret_cast<float4*>(out + (size_t)r * D) + lane * 2;
    dst[0] = make_float4(o0, o1, o2, o3);
    dst[1] = make_float4(o4, o5, o6, o7);
}

// ---------------------------------------------------------------------------
// Launch
// ---------------------------------------------------------------------------
extern "C" void kernel_launch(void* const* d_in, const int* in_sizes, int n_in,
                              void* d_out, int out_size) {
    const float* X    = (const float*)d_in[0];
    const int*   arow = (const int*)  d_in[1];
    const int*   acol = (const int*)  d_in[2];
    const float* aval = (const float*)d_in[3];
    const float* W    = (const float*)d_in[4];
    const float* bias = (const float*)d_in[5];
    float*       out  = (float*)d_out;

    int nE = in_sizes[1];
    if (nE > MAX_E) nE = MAX_E;

    // 1) support = X @ W  (fp16 m16n16k16 HMMA, fp32 accumulate, fp16 store)
    dim3 gemm_grid(D / 128, (N_NODES + 127) / 128);
    gemm_kernel<<<gemm_grid, 256>>>(X, W);

    // 2) CSR build (parallel scan, vectorized hist/build)
    zero_count_kernel<<<(N_NODES + 255) / 256, 256>>>();
    int nq = (nE + 3) / 4;
    hist_kernel<<<(nq + 255) / 256, 256>>>(arow, nE);
    scan1_kernel<<<SCAN_BLOCKS, 1024>>>();
    scan2_kernel<<<SCAN_BLOCKS, 1024>>>();
    build_kernel<<<(nq + 255) / 256, 256>>>(arow, acol, aval, nE);

    // 3) SpMM (warp per row), bias fused
    long long total_threads = (long long)N_NODES * 32;
    int nblk = (int)((total_threads + 255) / 256);
    spmm_kernel<<<nblk, 256>>>(bias, out);
}

// round 13
// speedup vs baseline: 2.2978x; 1.0488x over previous
#include <cuda_runtime.h>
#include <cuda_fp16.h>
#include <mma.h>
#include <cstdint>

using namespace nvcuda;

#define N_NODES 100000
#define D 256
#define MAX_E 3200000

#define SCAN_CHUNK 4096
#define SCAN_BLOCKS ((N_NODES + SCAN_CHUNK - 1) / SCAN_CHUNK)   // 25

#define GEMM_BLOCKS ((D / 128) * ((N_NODES + 127) / 128))       // 2*782 = 1564

// Static device scratch (allocation-free rule; zero-initialized at load)
__device__ __half g_support[(size_t)N_NODES * D];   // X @ W in fp16 (51.2 MB)
__device__ int    g_count [N_NODES];                // zeroed at end of each run
__device__ int    g_offset[N_NODES];
__device__ int    g_rank  [MAX_E];                  // within-row rank of each edge
__device__ int    g_bsum  [SCAN_BLOCKS];
__device__ uint2  g_csr   [MAX_E];                  // {col, val bits}

// ---------------------------------------------------------------------------
// Kernel 1 (block-specialized fusion):
//   blocks [0, GEMM_BLOCKS)      : fp16 m16n16k16 HMMA GEMM, fp32 acc, fp16 out
//   blocks [GEMM_BLOCKS, ...)    : edge histogram + rank capture
// The two halves touch disjoint data; no intra-kernel ordering required.
// ---------------------------------------------------------------------------
#define AS_LD 40     // halves: 80B row stride -> conflict-free 8-row bank cycle
#define BS_LD 136    // halves: 272B row stride
#define ST_LD 68     // floats

__global__ __launch_bounds__(256) void gemm_hist_kernel(const float* __restrict__ A,
                                                        const float* __restrict__ B,
                                                        const int* __restrict__ adj_row,
                                                        int nE) {
    __shared__ __align__(32) union {
        struct {
            __half As[128][AS_LD];
            __half Bs[32][BS_LD];
        } t;
        float staging[128][ST_LD];
    } sh;

    int tid = threadIdx.x;

    // ---------------- histogram half ----------------
    if (blockIdx.x >= GEMM_BLOCKS) {
        int hb = blockIdx.x - GEMM_BLOCKS;
        int i  = hb * 256 + tid;
        int e0 = i * 4;
        if (e0 + 3 < nE) {
            int4 r4 = *reinterpret_cast<const int4*>(adj_row + e0);
            int k0 = atomicAdd(&g_count[r4.x], 1);
            int k1 = atomicAdd(&g_count[r4.y], 1);
            int k2 = atomicAdd(&g_count[r4.z], 1);
            int k3 = atomicAdd(&g_count[r4.w], 1);
            *reinterpret_cast<int4*>(g_rank + e0) = make_int4(k0, k1, k2, k3);
        } else {
            for (int e = e0; e < nE; e++)
                g_rank[e] = atomicAdd(&g_count[adj_row[e]], 1);
        }
        return;
    }

    // ---------------- GEMM half ----------------
    int wid  = tid >> 5;
    int warp_m = wid >> 1;
    int warp_n = wid & 1;
    int blockRow = (blockIdx.x >> 1) * 128;
    int blockCol = (blockIdx.x & 1) * 128;

    wmma::fragment<wmma::accumulator, 16, 16, 16, float> acc[2][4];
    #pragma unroll
    for (int i = 0; i < 2; i++)
        #pragma unroll
        for (int j = 0; j < 4; j++)
            wmma::fill_fragment(acc[i][j], 0.0f);

    for (int k0 = 0; k0 < D; k0 += 32) {
        #pragma unroll
        for (int i = 0; i < 4; i++) {
            int f = tid + i * 256;
            int r = f >> 3;
            int c = (f & 7) * 4;
            int row = blockRow + r;
            float4 v = make_float4(0.f, 0.f, 0.f, 0.f);
            if (row < N_NODES)
                v = *reinterpret_cast<const float4*>(&A[(size_t)row * D + k0 + c]);
            __half2 h0 = __float22half2_rn(make_float2(v.x, v.y));
            __half2 h1 = __float22half2_rn(make_float2(v.z, v.w));
            *reinterpret_cast<uint2*>(&sh.t.As[r][c]) =
                make_uint2(*reinterpret_cast<unsigned*>(&h0), *reinterpret_cast<unsigned*>(&h1));
        }
        #pragma unroll
        for (int i = 0; i < 4; i++) {
            int f = tid + i * 256;
            int r = f >> 5;
            int c = (f & 31) * 4;
            float4 v = *reinterpret_cast<const float4*>(&B[(size_t)(k0 + r) * D + blockCol + c]);
            __half2 h0 = __float22half2_rn(make_float2(v.x, v.y));
            __half2 h1 = __float22half2_rn(make_float2(v.z, v.w));
            *reinterpret_cast<uint2*>(&sh.t.Bs[r][c]) =
                make_uint2(*reinterpret_cast<unsigned*>(&h0), *reinterpret_cast<unsigned*>(&h1));
        }
        __syncthreads();

        #pragma unroll
        for (int kk = 0; kk < 32; kk += 16) {
            wmma::fragment<wmma::matrix_a, 16, 16, 16, __half, wmma::row_major> a[2];
            wmma::load_matrix_sync(a[0], &sh.t.As[warp_m * 32][kk], AS_LD);
            wmma::load_matrix_sync(a[1], &sh.t.As[warp_m * 32 + 16][kk], AS_LD);
            #pragma unroll
            for (int j = 0; j < 4; j++) {
                wmma::fragment<wmma::matrix_b, 16, 16, 16, __half, wmma::row_major> b;
                wmma::load_matrix_sync(b, &sh.t.Bs[kk][warp_n * 64 + j * 16], BS_LD);
                wmma::mma_sync(acc[0][j], a[0], b, acc[0][j]);
                wmma::mma_sync(acc[1][j], a[1], b, acc[1][j]);
            }
        }
        __syncthreads();
    }

    #pragma unroll
    for (int phase = 0; phase < 2; phase++) {
        __syncthreads();
        if (warp_n == phase) {
            #pragma unroll
            for (int i = 0; i < 2; i++)
                #pragma unroll
                for (int j = 0; j < 4; j++)
                    wmma::store_matrix_sync(&sh.staging[warp_m * 32 + i * 16][j * 16],
                                            acc[i][j], ST_LD, wmma::mem_row_major);
        }
        __syncthreads();
        #pragma unroll
        for (int it = 0; it < 8; it++) {
            int f = tid + it * 256;
            int r  = f >> 4;
            int c4 = (f & 15) * 4;
            int row = blockRow + r;
            if (row < N_NODES) {
                float4 v = *reinterpret_cast<const float4*>(&sh.staging[r][c4]);
                __half2 h0 = __float22half2_rn(make_float2(v.x, v.y));
                __half2 h1 = __float22half2_rn(make_float2(v.z, v.w));
                uint2 pk = make_uint2(*reinterpret_cast<unsigned*>(&h0),
                                      *reinterpret_cast<unsigned*>(&h1));
                *reinterpret_cast<uint2*>(&g_support[(size_t)row * D + blockCol + phase * 64 + c4]) = pk;
            }
        }
    }
}

// ---------------------------------------------------------------------------
// Scan stage 1: per-block local exclusive scan of 4096 counts (4/thread).
// ---------------------------------------------------------------------------
__global__ __launch_bounds__(1024) void scan1_kernel() {
    __shared__ int sh[1024];
    int b = blockIdx.x, t = threadIdx.x;
    int base = b * SCAN_CHUNK + t * 4;

    int c[4];
    #pragma unroll
    for (int i = 0; i < 4; i++)
        c[i] = (base + i < N_NODES) ? g_count[base + i] : 0;
    int s = c[0] + c[1] + c[2] + c[3];

    sh[t] = s;
    __syncthreads();
    #pragma unroll
    for (int off = 1; off < 1024; off <<= 1) {
        int v = (t >= off) ? sh[t - off] : 0;
        __syncthreads();
        sh[t] += v;
        __syncthreads();
    }

    int run = (t == 0) ? 0 : sh[t - 1];
    #pragma unroll
    for (int i = 0; i < 4; i++) {
        if (base + i < N_NODES) g_offset[base + i] = run;
        run += c[i];
    }
    if (t == 1023) g_bsum[b] = sh[1023];
}

// ---------------------------------------------------------------------------
// Scan stage 2: add block-prefix; ALSO re-zero g_count so the next graph
// replay (and the first run, via zero static init) starts clean.
// ---------------------------------------------------------------------------
__global__ __launch_bounds__(1024) void scan2_kernel() {
    __shared__ int s_pre;
    int b = blockIdx.x, t = threadIdx.x;

    if (t < 32) {
        int s = 0;
        for (int i = t; i < b; i += 32) s += g_bsum[i];
        #pragma unroll
        for (int o = 16; o > 0; o >>= 1)
            s += __shfl_down_sync(0xFFFFFFFF, s, o);
        if (t == 0) s_pre = s;
    }
    __syncthreads();
    int pre = s_pre;

    int base = b * SCAN_CHUNK + t * 4;
    #pragma unroll
    for (int i = 0; i < 4; i++) {
        int idx = base + i;
        if (idx < N_NODES) {
            g_offset[idx] += pre;
            g_count[idx] = 0;          // reset for next execution
        }
    }
}

// ---------------------------------------------------------------------------
// Build: pos = offset[row] + rank[e]  (no atomics), 4 edges per thread.
// ---------------------------------------------------------------------------
__global__ __launch_bounds__(256) void build_kernel(const int* __restrict__ adj_row,
                                                    const int* __restrict__ adj_col,
                                                    const float* __restrict__ adj_val,
                                                    int nE) {
    int i = blockIdx.x * blockDim.x + threadIdx.x;
    int e0 = i * 4;
    if (e0 + 3 < nE) {
        int4   r4 = *reinterpret_cast<const int4*>(adj_row + e0);
        int4   c4 = *reinterpret_cast<const int4*>(adj_col + e0);
        float4 v4 = *reinterpret_cast<const float4*>(adj_val + e0);
        int4   k4 = *reinterpret_cast<const int4*>(g_rank + e0);
        g_csr[g_offset[r4.x] + k4.x] = make_uint2((unsigned)c4.x, __float_as_uint(v4.x));
        g_csr[g_offset[r4.y] + k4.y] = make_uint2((unsigned)c4.y, __float_as_uint(v4.y));
        g_csr[g_offset[r4.z] + k4.z] = make_uint2((unsigned)c4.z, __float_as_uint(v4.z));
        g_csr[g_offset[r4.w] + k4.w] = make_uint2((unsigned)c4.w, __float_as_uint(v4.w));
    } else {
        for (int e = e0; e < nE; e++) {
            g_csr[g_offset[adj_row[e]] + g_rank[e]] =
                make_uint2((unsigned)adj_col[e], __float_as_uint(adj_val[e]));
        }
    }
}

// ---------------------------------------------------------------------------
// CSR SpMM: warp per row, lane owns 8 halves (one 16B load per edge),
// 8-deep unrolled gather, fp32 accumulate, two accumulator banks, bias fused.
// Row extent from offset[r] / offset[r+1] (count array is already re-zeroed).
// ---------------------------------------------------------------------------
__device__ __forceinline__ void fma_halves(float acc[8], uint4 x, float v) {
    __half2* h = reinterpret_cast<__half2*>(&x);
    #pragma unroll
    for (int i = 0; i < 4; i++) {
        float2 f = __half22float2(h[i]);
        acc[i * 2 + 0] += f.x * v;
        acc[i * 2 + 1] += f.y * v;
    }
}

__global__ __launch_bounds__(256) void spmm_kernel(const float* __restrict__ bias,
                                                   float* __restrict__ out, int nE) {
    int gtid = blockIdx.x * blockDim.x + threadIdx.x;
    int r    = gtid >> 5;
    int lane = gtid & 31;
    if (r >= N_NODES) return;

    int start = g_offset[r];
    int end   = (r == N_NODES - 1) ? nE : g_offset[r + 1];

    float accA[8] = {};
    float accB[8] = {};

    int p = start;
    for (; p + 7 < end; p += 8) {
        uint2 e0 = g_csr[p + 0];
        uint2 e1 = g_csr[p + 1];
        uint2 e2 = g_csr[p + 2];
        uint2 e3 = g_csr[p + 3];
        uint2 e4 = g_csr[p + 4];
        uint2 e5 = g_csr[p + 5];
        uint2 e6 = g_csr[p + 6];
        uint2 e7 = g_csr[p + 7];
        uint4 x0 = *(reinterpret_cast<const uint4*>(g_support + (size_t)e0.x * D) + lane);
        uint4 x1 = *(reinterpret_cast<const uint4*>(g_support + (size_t)e1.x * D) + lane);
        uint4 x2 = *(reinterpret_cast<const uint4*>(g_support + (size_t)e2.x * D) + lane);
        uint4 x3 = *(reinterpret_cast<const uint4*>(g_support + (size_t)e3.x * D) + lane);
        uint4 x4 = *(reinterpret_cast<const uint4*>(g_support + (size_t)e4.x * D) + lane);
        uint4 x5 = *(reinterpret_cast<const uint4*>(g_support + (size_t)e5.x * D) + lane);
        uint4 x6 = *(reinterpret_cast<const uint4*>(g_support + (size_t)e6.x * D) + lane);
        uint4 x7 = *(reinterpret_cast<const uint4*>(g_support + (size_t)e7.x * D) + lane);
        fma_halves(accA, x0, __uint_as_float(e0.y));
        fma_halves(accB, x1, __uint_as_float(e1.y));
        fma_halves(accA, x2, __uint_as_float(e2.y));
        fma_halves(accB, x3, __uint_as_float(e3.y));
        fma_halves(accA, x4, __uint_as_float(e4.y));
        fma_halves(accB, x5, __uint_as_float(e5.y));
        fma_halves(accA, x6, __uint_as_float(e6.y));
        fma_halves(accB, x7, __uint_as_float(e7.y));
    }
    for (; p + 1 < end; p += 2) {
        uint2 e0 = g_csr[p + 0];
        uint2 e1 = g_csr[p + 1];
        uint4 x0 = *(reinterpret_cast<const uint4*>(g_support + (size_t)e0.x * D) + lane);
        uint4 x1 = *(reinterpret_cast<const uint4*>(g_support + (size_t)e1.x * D) + lane);
        fma_halves(accA, x0, __uint_as_float(e0.y));
        fma_halves(accB, x1, __uint_as_float(e1.y));
    }
    if (p < end) {
        uint2 e = g_csr[p];
        uint4 x = *(reinterpret_cast<const uint4*>(g_support + (size_t)e.x * D) + lane);
        fma_halves(accA, x, __uint_as_float(e.y));
    }

    const float4* bp = reinterpret_cast<const float4*>(bias) + lane * 2;
    float4 b0 = bp[0], b1 = bp[1];
    float o0 = accA[0] + accB[0] + b0.x;
    float o1 = accA[1] + accB[1] + b0.y;
    float o2 = accA[2] + accB[2] + b0.z;
    float o3 = accA[3] + accB[3] + b0.w;
    float o4 = accA[4] + accB[4] + b1.x;
    float o5 = accA[5] + accB[5] + b1.y;
    float o6 = accA[6] + accB[6] + b1.z;
    float o7 = accA[7] + accB[7] + b1.w;

    float4* dst = reinterpret_cast<float4*>(out + (size_t)r * D) + lane * 2;
    dst[0] = make_float4(o0, o1, o2, o3);
    dst[1] = make_float4(o4, o5, o6, o7);
}

// ---------------------------------------------------------------------------
// Launch
// ---------------------------------------------------------------------------
extern "C" void kernel_launch(void* const* d_in, const int* in_sizes, int n_in,
                              void* d_out, int out_size) {
    const float* X    = (const float*)d_in[0];
    const int*   arow = (const int*)  d_in[1];
    const int*   acol = (const int*)  d_in[2];
    const float* aval = (const float*)d_in[3];
    const float* W    = (const float*)d_in[4];
    const float* bias = (const float*)d_in[5];
    float*       out  = (float*)d_out;

    int nE = in_sizes[1];
    if (nE > MAX_E) nE = MAX_E;

    // 1) Fused: GEMM (tensor cores) + edge histogram/rank (block-specialized)
    int nq = (nE + 3) / 4;
    int hist_blocks = (nq + 255) / 256;
    gemm_hist_kernel<<<GEMM_BLOCKS + hist_blocks, 256>>>(X, W, arow, nE);

    // 2) Offsets (scan2 also re-zeroes counts for the next replay)
    scan1_kernel<<<SCAN_BLOCKS, 1024>>>();
    scan2_kernel<<<SCAN_BLOCKS, 1024>>>();

    // 3) CSR build (atomic-free via ranks)
    build_kernel<<<(nq + 255) / 256, 256>>>(arow, acol, aval, nE);

    // 4) SpMM (warp per row), bias fused
    long long total_threads = (long long)N_NODES * 32;
    int nblk = (int)((total_threads + 255) / 256);
    spmm_kernel<<<nblk, 256>>>(bias, out, nE);
}